// round 7
// baseline (speedup 1.0000x reference)
#include <cuda_runtime.h>
#include <cuda_bf16.h>
#include <cstdint>

typedef unsigned long long u64;

// ============================================================================
// Packed f32x2 primitives (sm_103a).
// ============================================================================
__device__ __forceinline__ u64 PK(float a, float b) {
    return ((u64)__float_as_uint(b) << 32) | (u64)__float_as_uint(a);
}
__device__ __forceinline__ float LO(u64 p) { return __uint_as_float((unsigned)p); }
__device__ __forceinline__ float HI(u64 p) { return __uint_as_float((unsigned)(p >> 32)); }

__device__ __forceinline__ u64 ADD2(u64 a, u64 b) {
    u64 r; asm("add.rn.f32x2 %0,%1,%2;" : "=l"(r) : "l"(a), "l"(b)); return r;
}
__device__ __forceinline__ u64 MUL2(u64 a, u64 b) {
    u64 r; asm("mul.rn.f32x2 %0,%1,%2;" : "=l"(r) : "l"(a), "l"(b)); return r;
}
__device__ __forceinline__ u64 FMA2(u64 a, u64 b, u64 c) {
    u64 r; asm("fma.rn.f32x2 %0,%1,%2,%3;" : "=l"(r) : "l"(a), "l"(b), "l"(c)); return r;
}
__device__ __forceinline__ u64 NEG2(u64 a) { return a ^ 0x8000000080000000ULL; }
__device__ __forceinline__ u64 ABS2(u64 a) { return a & 0x7FFFFFFF7FFFFFFFULL; }
__device__ __forceinline__ u64 SUB2(u64 a, u64 b) {   // exact: fma(b,-1,a)
    return FMA2(b, 0xBF800000BF800000ULL, a);
}

// ============================================================================
// double-float on packed lanes. Discipline (validated R2..R6):
//  - never dmul two UNNORMALIZED operands
//  - dadd_nr keeps exact two_sum residual, output counts as unnormalized
//  - dadd_ord: fast two-sum, requires |big.h| >= |small.h|
// ============================================================================
struct dd { u64 h, l; };
__device__ __forceinline__ dd mkdd(u64 h, u64 l) { dd r; r.h = h; r.l = l; return r; }

__device__ __forceinline__ dd dd_ts(u64 a, u64 b) {   // exact two_sum (normalized)
    u64 s  = ADD2(a, b);
    u64 bb = SUB2(s, a);
    u64 e  = ADD2(SUB2(a, SUB2(s, bb)), SUB2(b, bb));
    return mkdd(s, e);
}
__device__ __forceinline__ dd dadd(dd A, dd B) {      // full, renormalized (11)
    u64 s  = ADD2(A.h, B.h);
    u64 bb = SUB2(s, A.h);
    u64 e  = ADD2(SUB2(A.h, SUB2(s, bb)), SUB2(B.h, bb));
    u64 t  = ADD2(e, ADD2(A.l, B.l));
    u64 hh = ADD2(s, t);
    u64 ll = SUB2(t, SUB2(hh, s));
    return mkdd(hh, ll);
}
__device__ __forceinline__ dd dadd_nr(dd A, dd B) {   // no renorm (8)
    u64 s  = ADD2(A.h, B.h);
    u64 bb = SUB2(s, A.h);
    u64 e  = ADD2(SUB2(A.h, SUB2(s, bb)), SUB2(B.h, bb));
    u64 t  = ADD2(e, ADD2(A.l, B.l));
    return mkdd(s, t);
}
// fast ordered two-sum: requires |big.h| >= |small.h| (5)
__device__ __forceinline__ dd dadd_ord(dd big, dd small) {
    u64 s = ADD2(big.h, small.h);
    u64 e = SUB2(small.h, SUB2(s, big.h));
    u64 t = ADD2(e, ADD2(big.l, small.l));
    return mkdd(s, t);
}
__device__ __forceinline__ dd dneg(dd A) { return mkdd(NEG2(A.h), NEG2(A.l)); }
__device__ __forceinline__ dd dsub_nr(dd A, dd B) { return dadd_nr(A, dneg(B)); }
__device__ __forceinline__ dd renorm(dd A) {          // (3)
    u64 hh = ADD2(A.h, A.l);
    u64 ll = SUB2(A.l, SUB2(hh, A.h));
    return mkdd(hh, ll);
}
__device__ __forceinline__ dd dmul_s(dd A, dd B) {    // sloppy (4)
    u64 p = MUL2(A.h, B.h);
    u64 e = FMA2(A.h, B.h, NEG2(p));
    e = FMA2(A.h, B.l, e);
    e = FMA2(A.l, B.h, e);
    return mkdd(p, e);
}
__device__ __forceinline__ dd dmul_bl0(dd A, u64 Bh) { // B.l == 0 (3)
    u64 p = MUL2(A.h, Bh);
    u64 e = FMA2(A.h, Bh, NEG2(p));
    e = FMA2(A.l, Bh, e);
    return mkdd(p, e);
}
__device__ __forceinline__ dd dmul_al0(u64 Ah, dd B) { // A.l == 0 (3)
    u64 p = MUL2(Ah, B.h);
    u64 e = FMA2(Ah, B.h, NEG2(p));
    e = FMA2(Ah, B.l, e);
    return mkdd(p, e);
}
__device__ __forceinline__ dd dmul_exact(u64 Ah, u64 Bh) { // exact (2)
    u64 p = MUL2(Ah, Bh);
    u64 e = FMA2(Ah, Bh, NEG2(p));
    return mkdd(p, e);
}
__device__ __forceinline__ dd dscale(dd A, u64 p2) {
    return mkdd(MUL2(A.h, p2), MUL2(A.l, p2));
}
__device__ __forceinline__ dd ddbl(dd A) { return mkdd(ADD2(A.h, A.h), ADD2(A.l, A.l)); }
__device__ __forceinline__ dd drecip(dd B) {
    float bh0 = LO(B.h), bh1 = HI(B.h), bl0 = LO(B.l), bl1 = HI(B.l);
    float y0 = 1.0f / bh0, y1 = 1.0f / bh1;
    float r0 = fmaf(bh0, y0, -1.0f); r0 = fmaf(bl0, y0, r0);
    float r1 = fmaf(bh1, y1, -1.0f); r1 = fmaf(bl1, y1, r1);
    return mkdd(PK(y0, y1), PK(-y0 * r0, -y1 * r1));
}
__device__ __forceinline__ u64 collapse(dd A) { return ADD2(A.h, A.l); }
#define DDC(x) mkdd(PK((float)(x), (float)(x)), \
                    PK((float)((x) - (double)(float)(x)), (float)((x) - (double)(float)(x))))

// ============================================================================
// One thread = TWO matrices. Cayley-Hamilton reduced expm.
// A kept UNSCALED; scaling folded into p, q and final coefficients.
// ============================================================================
__global__ __launch_bounds__(128, 7)
void lie_expm_kernel(const float* __restrict__ v, float* __restrict__ out, int B) {
    int i = blockIdx.x * blockDim.x + threadIdx.x;
    int B2 = (B + 1) >> 1;
    if (i >= B2) return;
    int i0 = 2 * i;
    int i1 = min(2 * i + 1, B - 1);
    bool w1 = (2 * i + 1) < B;

    const float4* vp0 = reinterpret_cast<const float4*>(v + (size_t)i0 * 8);
    const float4* vp1 = reinterpret_cast<const float4*>(v + (size_t)i1 * 8);
    float4 x0 = vp0[0], x1 = vp0[1];
    float4 y0 = vp1[0], y1 = vp1[1];

    u64 V0 = PK(x0.x, y0.x), V1 = PK(x0.y, y0.y), V2 = PK(x0.z, y0.z), V3 = PK(x0.w, y0.w);
    u64 V4 = PK(x1.x, y1.x), V5 = PK(x1.y, y1.y), V6 = PK(x1.z, y1.z), V7 = PK(x1.w, y1.w);

    // Unscaled A (traceless). T0,T1,T3,T4 full dd; rest exact fp32.
    dd T0 = dd_ts(V3, V4);
    dd T1 = dd_ts(V5, NEG2(V2));
    dd T3 = dd_ts(V2, V5);
    dd T4 = dd_ts(V3, NEG2(V4));
    u64 T2 = V0, T5 = V1, T6 = V6, T7 = V7;
    u64 T8 = MUL2(V3, PK(-2.0f, -2.0f));   // exact

    // inf-norm over both lanes
    u64 r0 = ADD2(ADD2(ABS2(T0.h), ABS2(T1.h)), ABS2(T2));
    u64 r1 = ADD2(ADD2(ABS2(T3.h), ABS2(T4.h)), ABS2(T5));
    u64 r2 = ADD2(ADD2(ABS2(T6), ABS2(T7)), ABS2(T8));
    float n = fmaxf(fmaxf(fmaxf(LO(r0), HI(r0)), fmaxf(LO(r1), HI(r1))),
                    fmaxf(LO(r2), HI(r2)));

    // warp-uniform scaling count (theta = 1)
    int mx = __reduce_max_sync(0xffffffffu, __float_as_int(n));
    float nw = __int_as_float(mx);
    int s = 0;
    if (nw > 1.0f) {
        s = (int)ceilf(log2f(nw));
        s = min(max(s, 0), 20);
    }
    uint32_t s1b = (uint32_t)(127 - s) << 23;        // 2^-s
    uint32_t s2b = (uint32_t)(127 - 2 * s) << 23;    // 4^-s
    uint32_t s3b = (uint32_t)(127 - 3 * s) << 23;    // 8^-s
    u64 sc1 = ((u64)s1b << 32) | s1b;
    u64 sc2 = ((u64)s2b << 32) | s2b;
    u64 sc3 = ((u64)s3b << 32) | s3b;

    // p_A = tr(A^2)/2 ; q_A = det(A) ; t222 = (A^2)_22 — all on UNSCALED A
    dd d88 = dmul_exact(T8, T8);
    dd d57 = dmul_exact(T5, T7);
    dd tdiag = dadd_nr(dadd_nr(dmul_s(T0, T0), dmul_s(T4, T4)), d88);
    dd toff  = dadd_nr(dadd_nr(dmul_s(T1, T3), dmul_exact(T2, T6)), d57);
    dd pA = dadd_nr(dscale(tdiag, PK(0.5f, 0.5f)), toff);

    dd m0 = dsub_nr(dmul_bl0(T4, T8), d57);
    dd m1 = dsub_nr(dmul_bl0(T3, T8), dmul_exact(T5, T6));
    dd m2 = dsub_nr(dmul_bl0(T3, T7), dmul_bl0(T4, T6));
    dd qA = dadd(dadd_nr(dmul_s(T0, renorm(m0)), dneg(dmul_s(T1, renorm(m1)))),
                 dmul_al0(T2, renorm(m2)));

    dd t222 = dadd(dadd_nr(dmul_exact(T6, T2), dmul_exact(T7, T5)), d88);

    // scaled invariants: p = pA*4^-s, q = qA*8^-s (exact power-of-two scales)
    dd p = renorm(dscale(pA, sc2));
    dd q = dscale(qA, sc3);   // qA already normalized

    // deg-11 Taylor Horner in Cayley-Hamilton reduced space.
    // Ordered adds: |CK[k]| >= |a2*q| and |a0| >= |a2*p| (factorial ratios).
    dd a0 = DDC(1.0 / 362880.0);     // C9
    dd a1 = DDC(1.0 / 3628800.0);    // C10
    dd a2 = DDC(1.0 / 39916800.0);   // C11
    const dd CK[9] = {
        DDC(1.0 / 40320.0), DDC(1.0 / 5040.0), DDC(1.0 / 720.0),
        DDC(1.0 / 120.0),   DDC(1.0 / 24.0),   DDC(1.0 / 6.0),
        DDC(0.5),           DDC(1.0),          DDC(1.0)
    };
#pragma unroll
    for (int k = 0; k < 9; k++) {
        dd n0 = dadd_ord(CK[k], dmul_s(a2, q));
        dd n1 = dadd_ord(a0, dmul_s(a2, p));
        a2 = a1;
        a1 = n1;
        a0 = n0;
    }
    a0 = renorm(a0); a1 = renorm(a1); a2 = renorm(a2);

    // s squarings: (a0 + a1 L + a2 L^2)^2 mod (L^3 - pL - q)
    for (int it = 0; it < s; it++) {
        dd s00 = dmul_s(a0, a0);
        dd s11 = dmul_s(a1, a1);
        dd s22 = dmul_s(a2, a2);
        dd s01 = dmul_s(a0, a1);
        dd s02 = dmul_s(a0, a2);
        dd t12 = ddbl(dmul_s(a1, a2));
        dd b0 = dadd(s00, dmul_s(t12, q));
        dd b1 = dadd(dadd_nr(ddbl(s01), dmul_s(t12, p)), dmul_s(s22, q));
        dd b2 = dadd(dadd_nr(s11, ddbl(s02)), dmul_s(s22, p));
        a0 = b0; a1 = b1; a2 = b2;
    }

    // fold 2^-s into a1, 4^-s into a2 (H = a0 I + a1s A + a2s A^2)
    dd a1s = dscale(a1, sc1);
    dd a2s = dscale(a2, sc2);

    // H22 = a0 + a1s*A8 + a2s*t222
    dd h22 = dadd(dadd_nr(dmul_bl0(a1s, T8), dmul_s(a2s, t222)), a0);
    dd inv = drecip(h22);

    // fold 1/H22 into coefficients
    dd b0c = dmul_s(a0, inv);
    dd b1c = dmul_s(a1s, inv);
    dd b2c = dmul_s(a2s, inv);

    // M = b1 I + b2 A
    dd M0 = dadd_nr(dmul_s(b2c, T0), b1c);
    dd M1 = dmul_s(b2c, T1);
    dd M2 = dmul_bl0(b2c, T2);
    dd M3 = dmul_s(b2c, T3);
    dd M4 = dadd_nr(dmul_s(b2c, T4), b1c);
    dd M5 = dmul_bl0(b2c, T5);
    dd M6 = dmul_bl0(b2c, T6);
    dd M7 = dmul_bl0(b2c, T7);
    dd M8 = dadd_nr(dmul_bl0(b2c, T8), b1c);

    // H/H22 = b0 I + A*M ; entry (2,2) is exactly 1.
    u64 h[8];
    h[0] = collapse(dadd_nr(dadd_nr(dadd_nr(dmul_s(T0, M0), dmul_s(T1, M3)),
                                    dmul_al0(T2, M6)), b0c));
    h[1] = collapse(dadd_nr(dadd_nr(dmul_s(T0, M1), dmul_s(T1, M4)),
                            dmul_al0(T2, M7)));
    h[2] = collapse(dadd_nr(dadd_nr(dmul_s(T0, M2), dmul_s(T1, M5)),
                            dmul_al0(T2, M8)));
    h[3] = collapse(dadd_nr(dadd_nr(dmul_s(T3, M0), dmul_s(T4, M3)),
                            dmul_al0(T5, M6)));
    h[4] = collapse(dadd_nr(dadd_nr(dadd_nr(dmul_s(T3, M1), dmul_s(T4, M4)),
                                    dmul_al0(T5, M7)), b0c));
    h[5] = collapse(dadd_nr(dadd_nr(dmul_s(T3, M2), dmul_s(T4, M5)),
                            dmul_al0(T5, M8)));
    h[6] = collapse(dadd_nr(dadd_nr(dmul_al0(T6, M0), dmul_al0(T7, M3)),
                            dmul_al0(T8, M6)));
    h[7] = collapse(dadd_nr(dadd_nr(dmul_al0(T6, M1), dmul_al0(T7, M4)),
                            dmul_al0(T8, M7)));

    // stores: 9 float2 covering both items
    float2* o2 = reinterpret_cast<float2*>(out + (size_t)i0 * 9);
    o2[0] = make_float2(LO(h[0]), LO(h[1]));
    o2[1] = make_float2(LO(h[2]), LO(h[3]));
    o2[2] = make_float2(LO(h[4]), LO(h[5]));
    o2[3] = make_float2(LO(h[6]), LO(h[7]));
    if (w1) {
        o2[4] = make_float2(1.0f, HI(h[0]));
        o2[5] = make_float2(HI(h[1]), HI(h[2]));
        o2[6] = make_float2(HI(h[3]), HI(h[4]));
        o2[7] = make_float2(HI(h[5]), HI(h[6]));
        o2[8] = make_float2(HI(h[7]), 1.0f);
    } else {
        out[(size_t)i0 * 9 + 8] = 1.0f;
    }
}

extern "C" void kernel_launch(void* const* d_in, const int* in_sizes, int n_in,
                              void* d_out, int out_size) {
    const float* v = (const float*)d_in[0];
    float* out = (float*)d_out;
    int B = in_sizes[0] / 8;
    int B2 = (B + 1) / 2;
    int threads = 128;
    int blocks = (B2 + threads - 1) / threads;
    lie_expm_kernel<<<blocks, threads>>>(v, out, B);
}

// round 8
// speedup vs baseline: 1.3364x; 1.3364x over previous
#include <cuda_runtime.h>
#include <cuda_bf16.h>
#include <cstdint>

typedef unsigned long long u64;

// ============================================================================
// Packed f32x2 primitives (sm_103a).
// ============================================================================
__device__ __forceinline__ u64 PK(float a, float b) {
    return ((u64)__float_as_uint(b) << 32) | (u64)__float_as_uint(a);
}
__device__ __forceinline__ float LO(u64 p) { return __uint_as_float((unsigned)p); }
__device__ __forceinline__ float HI(u64 p) { return __uint_as_float((unsigned)(p >> 32)); }

__device__ __forceinline__ u64 ADD2(u64 a, u64 b) {
    u64 r; asm("add.rn.f32x2 %0,%1,%2;" : "=l"(r) : "l"(a), "l"(b)); return r;
}
__device__ __forceinline__ u64 MUL2(u64 a, u64 b) {
    u64 r; asm("mul.rn.f32x2 %0,%1,%2;" : "=l"(r) : "l"(a), "l"(b)); return r;
}
__device__ __forceinline__ u64 FMA2(u64 a, u64 b, u64 c) {
    u64 r; asm("fma.rn.f32x2 %0,%1,%2,%3;" : "=l"(r) : "l"(a), "l"(b), "l"(c)); return r;
}
__device__ __forceinline__ u64 NEG2(u64 a) { return a ^ 0x8000000080000000ULL; }
__device__ __forceinline__ u64 ABS2(u64 a) { return a & 0x7FFFFFFF7FFFFFFFULL; }
__device__ __forceinline__ u64 SUB2(u64 a, u64 b) {   // exact: fma(b,-1,a)
    return FMA2(b, 0xBF800000BF800000ULL, a);
}

// ============================================================================
// double-float on packed lanes (discipline validated R2..R7):
//  - never dmul two UNNORMALIZED operands
//  - dadd_nr keeps exact two_sum residual; output counts as unnormalized
//  - dadd_ord requires |big.h| >= |small.h|
// ============================================================================
struct dd { u64 h, l; };
__device__ __forceinline__ dd mkdd(u64 h, u64 l) { dd r; r.h = h; r.l = l; return r; }

__device__ __forceinline__ dd dd_ts(u64 a, u64 b) {   // exact two_sum (normalized)
    u64 s  = ADD2(a, b);
    u64 bb = SUB2(s, a);
    u64 e  = ADD2(SUB2(a, SUB2(s, bb)), SUB2(b, bb));
    return mkdd(s, e);
}
__device__ __forceinline__ dd dadd(dd A, dd B) {      // full, renormalized (11)
    u64 s  = ADD2(A.h, B.h);
    u64 bb = SUB2(s, A.h);
    u64 e  = ADD2(SUB2(A.h, SUB2(s, bb)), SUB2(B.h, bb));
    u64 t  = ADD2(e, ADD2(A.l, B.l));
    u64 hh = ADD2(s, t);
    u64 ll = SUB2(t, SUB2(hh, s));
    return mkdd(hh, ll);
}
__device__ __forceinline__ dd dadd_nr(dd A, dd B) {   // no renorm (8)
    u64 s  = ADD2(A.h, B.h);
    u64 bb = SUB2(s, A.h);
    u64 e  = ADD2(SUB2(A.h, SUB2(s, bb)), SUB2(B.h, bb));
    u64 t  = ADD2(e, ADD2(A.l, B.l));
    return mkdd(s, t);
}
__device__ __forceinline__ dd dadd_ord(dd big, dd small) { // |big.h|>=|small.h| (5)
    u64 s = ADD2(big.h, small.h);
    u64 e = SUB2(small.h, SUB2(s, big.h));
    u64 t = ADD2(e, ADD2(big.l, small.l));
    return mkdd(s, t);
}
__device__ __forceinline__ dd dneg(dd A) { return mkdd(NEG2(A.h), NEG2(A.l)); }
__device__ __forceinline__ dd dsub_nr(dd A, dd B) { return dadd_nr(A, dneg(B)); }
__device__ __forceinline__ dd renorm(dd A) {          // (3)
    u64 hh = ADD2(A.h, A.l);
    u64 ll = SUB2(A.l, SUB2(hh, A.h));
    return mkdd(hh, ll);
}
__device__ __forceinline__ dd dmul_s(dd A, dd B) {    // sloppy (4)
    u64 p = MUL2(A.h, B.h);
    u64 e = FMA2(A.h, B.h, NEG2(p));
    e = FMA2(A.h, B.l, e);
    e = FMA2(A.l, B.h, e);
    return mkdd(p, e);
}
__device__ __forceinline__ dd dmul_bl0(dd A, u64 Bh) { // B.l == 0 (3)
    u64 p = MUL2(A.h, Bh);
    u64 e = FMA2(A.h, Bh, NEG2(p));
    e = FMA2(A.l, Bh, e);
    return mkdd(p, e);
}
__device__ __forceinline__ dd dmul_al0(u64 Ah, dd B) { // A.l == 0 (3)
    u64 p = MUL2(Ah, B.h);
    u64 e = FMA2(Ah, B.h, NEG2(p));
    e = FMA2(Ah, B.l, e);
    return mkdd(p, e);
}
__device__ __forceinline__ dd dmul_exact(u64 Ah, u64 Bh) { // exact (2)
    u64 p = MUL2(Ah, Bh);
    u64 e = FMA2(Ah, Bh, NEG2(p));
    return mkdd(p, e);
}
__device__ __forceinline__ dd dscale(dd A, u64 p2) {
    return mkdd(MUL2(A.h, p2), MUL2(A.l, p2));
}
__device__ __forceinline__ dd ddbl(dd A) { return mkdd(ADD2(A.h, A.h), ADD2(A.l, A.l)); }
__device__ __forceinline__ u64 collapse(dd A) { return ADD2(A.h, A.l); }
#define DDC(x) mkdd(PK((float)(x), (float)(x)), \
                    PK((float)((x) - (double)(float)(x)), (float)((x) - (double)(float)(x))))

// ============================================================================
// One thread = TWO matrices. Cayley-Hamilton reduced expm.
// dd upstream (amplified by squaring); fp32 packed downstream (not amplified).
// ============================================================================
__global__ __launch_bounds__(128, 8)
void lie_expm_kernel(const float* __restrict__ v, float* __restrict__ out, int B) {
    int i = blockIdx.x * blockDim.x + threadIdx.x;
    int B2 = (B + 1) >> 1;
    if (i >= B2) return;
    int i0 = 2 * i;
    int i1 = min(2 * i + 1, B - 1);
    bool w1 = (2 * i + 1) < B;

    const float4* vp0 = reinterpret_cast<const float4*>(v + (size_t)i0 * 8);
    const float4* vp1 = reinterpret_cast<const float4*>(v + (size_t)i1 * 8);
    float4 x0 = vp0[0], x1 = vp0[1];
    float4 y0 = vp1[0], y1 = vp1[1];

    u64 V0 = PK(x0.x, y0.x), V1 = PK(x0.y, y0.y), V2 = PK(x0.z, y0.z), V3 = PK(x0.w, y0.w);
    u64 V4 = PK(x1.x, y1.x), V5 = PK(x1.y, y1.y), V6 = PK(x1.z, y1.z), V7 = PK(x1.w, y1.w);

    // Unscaled A (traceless). T0,T1,T3,T4 full dd; rest exact fp32.
    dd T0 = dd_ts(V3, V4);
    dd T1 = dd_ts(V5, NEG2(V2));
    dd T3 = dd_ts(V2, V5);
    dd T4 = dd_ts(V3, NEG2(V4));
    u64 T2 = V0, T5 = V1, T6 = V6, T7 = V7;
    u64 T8 = MUL2(V3, PK(-2.0f, -2.0f));   // exact

    // inf-norm over both lanes
    u64 r0 = ADD2(ADD2(ABS2(T0.h), ABS2(T1.h)), ABS2(T2));
    u64 r1 = ADD2(ADD2(ABS2(T3.h), ABS2(T4.h)), ABS2(T5));
    u64 r2 = ADD2(ADD2(ABS2(T6), ABS2(T7)), ABS2(T8));
    float n = fmaxf(fmaxf(fmaxf(LO(r0), HI(r0)), fmaxf(LO(r1), HI(r1))),
                    fmaxf(LO(r2), HI(r2)));

    // warp-uniform scaling count (theta = 1)
    int mx = __reduce_max_sync(0xffffffffu, __float_as_int(n));
    float nw = __int_as_float(mx);
    int s = 0;
    if (nw > 1.0f) {
        s = (int)ceilf(log2f(nw));
        s = min(max(s, 0), 20);
    }
    uint32_t s1b = (uint32_t)(127 - s) << 23;        // 2^-s
    uint32_t s2b = (uint32_t)(127 - 2 * s) << 23;    // 4^-s
    uint32_t s3b = (uint32_t)(127 - 3 * s) << 23;    // 8^-s
    u64 sc1 = ((u64)s1b << 32) | s1b;
    u64 sc2 = ((u64)s2b << 32) | s2b;
    u64 sc3 = ((u64)s3b << 32) | s3b;

    // p_A = tr(A^2)/2 ; q_A = det(A) on UNSCALED A (dd: amplified upstream)
    {
        // scoped so temporaries die before the squaring loop
    }
    dd p, q;
    {
        dd d88 = dmul_exact(T8, T8);
        dd d57 = dmul_exact(T5, T7);
        dd tdiag = dadd_nr(dadd_nr(dmul_s(T0, T0), dmul_s(T4, T4)), d88);
        dd toff  = dadd_nr(dadd_nr(dmul_s(T1, T3), dmul_exact(T2, T6)), d57);
        dd pA = dadd_nr(dscale(tdiag, PK(0.5f, 0.5f)), toff);

        dd m0 = dsub_nr(dmul_bl0(T4, T8), d57);
        dd m1 = dsub_nr(dmul_bl0(T3, T8), dmul_exact(T5, T6));
        dd m2 = dsub_nr(dmul_bl0(T3, T7), dmul_bl0(T4, T6));
        dd qA = dadd(dadd_nr(dmul_s(T0, renorm(m0)), dneg(dmul_s(T1, renorm(m1)))),
                     dmul_al0(T2, renorm(m2)));

        p = renorm(dscale(pA, sc2));   // pA*4^-s (exact scale)
        q = dscale(qA, sc3);           // qA*8^-s (qA normalized)
    }

    // deg-11 Taylor Horner in Cayley-Hamilton reduced space (ordered adds
    // valid at theta=1: |CK[k]| >= |a2*q|, |a0| >= |a2*p|).
    dd a0 = DDC(1.0 / 362880.0);     // C9
    dd a1 = DDC(1.0 / 3628800.0);    // C10
    dd a2 = DDC(1.0 / 39916800.0);   // C11
    const dd CK[9] = {
        DDC(1.0 / 40320.0), DDC(1.0 / 5040.0), DDC(1.0 / 720.0),
        DDC(1.0 / 120.0),   DDC(1.0 / 24.0),   DDC(1.0 / 6.0),
        DDC(0.5),           DDC(1.0),          DDC(1.0)
    };
#pragma unroll
    for (int k = 0; k < 9; k++) {
        dd n0 = dadd_ord(CK[k], dmul_s(a2, q));
        dd n1 = dadd_ord(a0, dmul_s(a2, p));
        a2 = a1;
        a1 = n1;
        a0 = n0;
    }
    a0 = renorm(a0); a1 = renorm(a1); a2 = renorm(a2);

    // s squarings: (a0 + a1 L + a2 L^2)^2 mod (L^3 - pL - q)
    for (int it = 0; it < s; it++) {
        dd s00 = dmul_s(a0, a0);
        dd s11 = dmul_s(a1, a1);
        dd s22 = dmul_s(a2, a2);
        dd s01 = dmul_s(a0, a1);
        dd s02 = dmul_s(a0, a2);
        dd t12 = ddbl(dmul_s(a1, a2));
        dd b0 = dadd(s00, dmul_s(t12, q));
        dd b1 = dadd(dadd_nr(ddbl(s01), dmul_s(t12, p)), dmul_s(s22, q));
        dd b2 = dadd(dadd_nr(s11, ddbl(s02)), dmul_s(s22, p));
        a0 = b0; a1 = b1; a2 = b2;
    }

    // fold 2^-s into a1, 4^-s into a2:  H = a0 I + a1s A + a2s A^2
    dd a1s = dscale(a1, sc1);
    dd a2s = dscale(a2, sc2);

    // H22 in dd (its relative error multiplies every output)
    dd t222 = dadd(dadd_nr(dmul_exact(T6, T2), dmul_exact(T7, T5)),
                   dmul_exact(T8, T8));
    dd h22  = dadd(dadd_nr(dmul_bl0(a1s, T8), dmul_s(a2s, t222)), a0);

    // fp32 reciprocal, fp32-accurate (one Newton step against dd H22)
    float bh0 = LO(h22.h), bh1 = HI(h22.h), bl0 = LO(h22.l), bl1 = HI(h22.l);
    float yy0 = 1.0f / bh0, yy1 = 1.0f / bh1;
    float rr0 = fmaf(bh0, yy0, -1.0f); rr0 = fmaf(bl0, yy0, rr0);
    float rr1 = fmaf(bh1, yy1, -1.0f); rr1 = fmaf(bl1, yy1, rr1);
    u64 invf = PK(fmaf(-yy0, rr0, yy0), fmaf(-yy1, rr1, yy1));

    // ---- fp32 packed reconstruction (errors here are NOT amplified) ----
    u64 b0f = MUL2(collapse(a0),  invf);
    u64 b1f = MUL2(collapse(a1s), invf);
    u64 b2f = MUL2(collapse(a2s), invf);

    u64 M0 = FMA2(b2f, T0.h, b1f);
    u64 M1 = MUL2(b2f, T1.h);
    u64 M2 = MUL2(b2f, T2);
    u64 M3 = MUL2(b2f, T3.h);
    u64 M4 = FMA2(b2f, T4.h, b1f);
    u64 M5 = MUL2(b2f, T5);
    u64 M6 = MUL2(b2f, T6);
    u64 M7 = MUL2(b2f, T7);
    u64 M8 = FMA2(b2f, T8, b1f);

    u64 h[8];
    h[0] = ADD2(FMA2(T0.h, M0, FMA2(T1.h, M3, MUL2(T2, M6))), b0f);
    h[1] = FMA2(T0.h, M1, FMA2(T1.h, M4, MUL2(T2, M7)));
    h[2] = FMA2(T0.h, M2, FMA2(T1.h, M5, MUL2(T2, M8)));
    h[3] = FMA2(T3.h, M0, FMA2(T4.h, M3, MUL2(T5, M6)));
    h[4] = ADD2(FMA2(T3.h, M1, FMA2(T4.h, M4, MUL2(T5, M7))), b0f);
    h[5] = FMA2(T3.h, M2, FMA2(T4.h, M5, MUL2(T5, M8)));
    h[6] = FMA2(T6, M0, FMA2(T7, M3, MUL2(T8, M6)));
    h[7] = FMA2(T6, M1, FMA2(T7, M4, MUL2(T8, M7)));

    // stores: 9 float2 covering both items; (2,2) is exactly 1.
    float2* o2 = reinterpret_cast<float2*>(out + (size_t)i0 * 9);
    o2[0] = make_float2(LO(h[0]), LO(h[1]));
    o2[1] = make_float2(LO(h[2]), LO(h[3]));
    o2[2] = make_float2(LO(h[4]), LO(h[5]));
    o2[3] = make_float2(LO(h[6]), LO(h[7]));
    if (w1) {
        o2[4] = make_float2(1.0f, HI(h[0]));
        o2[5] = make_float2(HI(h[1]), HI(h[2]));
        o2[6] = make_float2(HI(h[3]), HI(h[4]));
        o2[7] = make_float2(HI(h[5]), HI(h[6]));
        o2[8] = make_float2(HI(h[7]), 1.0f);
    } else {
        out[(size_t)i0 * 9 + 8] = 1.0f;
    }
}

extern "C" void kernel_launch(void* const* d_in, const int* in_sizes, int n_in,
                              void* d_out, int out_size) {
    const float* v = (const float*)d_in[0];
    float* out = (float*)d_out;
    int B = in_sizes[0] / 8;
    int B2 = (B + 1) / 2;
    int threads = 128;
    int blocks = (B2 + threads - 1) / threads;
    lie_expm_kernel<<<blocks, threads>>>(v, out, B);
}